// round 12
// baseline (speedup 1.0000x reference)
#include <cuda_runtime.h>

#define NB 64
#define NH 16
#define TAU 1.0f

__device__ unsigned int g_segmax[NB * NH];  // float bits; all >= 0 (post-ReLU)
__device__ float g_gate[NB];

// ---------- packed f32x2 helpers ----------
__device__ __forceinline__ unsigned long long pack2(float lo, float hi) {
    unsigned long long r;
    asm("mov.b64 %0, {%1, %2};" : "=l"(r) : "f"(lo), "f"(hi));
    return r;
}
__device__ __forceinline__ float2 unpack2(unsigned long long p) {
    float2 f;
    asm("mov.b64 {%0, %1}, %2;" : "=f"(f.x), "=f"(f.y) : "l"(p));
    return f;
}
__device__ __forceinline__ unsigned long long fma2(unsigned long long a,
                                                   unsigned long long b,
                                                   unsigned long long c) {
    unsigned long long d;
    asm("fma.rn.f32x2 %0, %1, %2, %3;" : "=l"(d) : "l"(a), "l"(b), "l"(c));
    return d;
}
__device__ __forceinline__ unsigned long long relu2(unsigned long long p) {
    float2 f = unpack2(p);
    return pack2(fmaxf(f.x, 0.0f), fmaxf(f.y, 0.0f));
}
__device__ __forceinline__ float lo2(unsigned long long p) { return unpack2(p).x; }

// ---------- kernels ----------
__global__ void init_kernel() {
    int i = threadIdx.x;
    if (i < NB * NH) g_segmax[i] = 0u;
}

__global__ void dummyA_kernel() {}
__global__ void dummyB_kernel() {}

__global__ __launch_bounds__(256, 3) void mlp_seg_kernel(
    const float* __restrict__ pos, const float* __restrict__ refl,
    const int* __restrict__ batch,
    const float* __restrict__ W1, const float* __restrict__ b1,
    const float* __restrict__ W2, const float* __restrict__ b2,
    int n)
{
    // weights pre-duplicated into b64 pairs so one LDS.64 feeds both packed halves
    __shared__ unsigned long long sW1[4 * NH];
    __shared__ unsigned long long sB1[NH];
    __shared__ unsigned long long sW2[NH * NH];
    __shared__ unsigned long long sB2[NH];

    for (int i = threadIdx.x; i < 4 * NH + NH + NH * NH + NH; i += blockDim.x) {
        float w;
        if (i < 64)       { w = W1[i];       sW1[i]       = pack2(w, w); }
        else if (i < 80)  { w = b1[i - 64];  sB1[i - 64]  = pack2(w, w); }
        else if (i < 336) { w = W2[i - 80];  sW2[i - 80]  = pack2(w, w); }
        else              { w = b2[i - 336]; sB2[i - 336] = pack2(w, w); }
    }
    __syncthreads();

    const int t = blockIdx.x * blockDim.x + threadIdx.x;
    const long base = 4L * t;
    const bool full4 = (base + 3 < (long)n);
    const int lane = threadIdx.x & 31;

    if (!full4) {
        // tail: fully scalar (usually never taken: N % 4 == 0)
        for (long p = base; p < (long)n; ++p) {
            float f[4] = {pos[3 * p + 0], pos[3 * p + 1], pos[3 * p + 2], refl[p]};
            float h1[NH];
            #pragma unroll
            for (int j = 0; j < NH; j++) {
                float s = lo2(sB1[j]);
                #pragma unroll
                for (int k = 0; k < 4; k++) s += f[k] * lo2(sW1[k * NH + j]);
                h1[j] = fmaxf(s, 0.0f);
            }
            int sgi = batch[p];
            #pragma unroll
            for (int j = 0; j < NH; j++) {
                float s = lo2(sB2[j]);
                #pragma unroll
                for (int k = 0; k < NH; k++) s += h1[k] * lo2(sW2[k * NH + j]);
                s = fmaxf(s, 0.0f);
                atomicMax(&g_segmax[sgi * NH + j], __float_as_uint(s));
            }
        }
        return;
    }

    const float4* pos4 = reinterpret_cast<const float4*>(pos);
    float4 v0 = pos4[3 * t + 0];
    float4 v1 = pos4[3 * t + 1];
    float4 v2 = pos4[3 * t + 2];
    float4 r  = reinterpret_cast<const float4*>(refl)[t];
    int4  bb  = reinterpret_cast<const int4*>(batch)[t];

    // warp-uniform segment check (batch sorted: bb.x == bb.w => all 4 equal)
    const int  wseg = __shfl_sync(0xffffffffu, bb.x, 0);
    const bool wuni = __all_sync(0xffffffffu, (bb.x == bb.w) && (bb.x == wseg));

    // pack features for both pairs upfront; source float4s then die
    unsigned long long fp[2][4];
    fp[0][0] = pack2(v0.x, v0.w); fp[0][1] = pack2(v0.y, v1.x);
    fp[0][2] = pack2(v0.z, v1.y); fp[0][3] = pack2(r.x,  r.y);
    fp[1][0] = pack2(v1.z, v2.y); fp[1][1] = pack2(v1.w, v2.z);
    fp[1][2] = pack2(v2.x, v2.w); fp[1][3] = pack2(r.z,  r.w);

    if (wuni) {
        unsigned keep = 0u;  // lane j (<16) holds warp-max of feature j over both pairs
        #pragma unroll
        for (int p = 0; p < 2; p++) {
            // layer 1 for this pair only: a[16] u64 = 32 regs live
            unsigned long long a[NH];
            #pragma unroll
            for (int j = 0; j < NH; j++) a[j] = sB1[j];
            #pragma unroll
            for (int k = 0; k < 4; k++) {
                #pragma unroll
                for (int j = 0; j < NH; j++)
                    a[j] = fma2(fp[p][k], sW1[k * NH + j], a[j]);
            }
            #pragma unroll
            for (int j = 0; j < NH; j++) a[j] = relu2(a[j]);

            // layer 2 in quarters: c[4] u64 = 8 regs live
            #pragma unroll
            for (int q = 0; q < 4; q++) {
                unsigned long long c[4];
                #pragma unroll
                for (int j = 0; j < 4; j++) c[j] = sB2[q * 4 + j];
                #pragma unroll
                for (int k = 0; k < NH; k++) {
                    #pragma unroll
                    for (int j = 0; j < 4; j++)
                        c[j] = fma2(a[k], sW2[k * NH + q * 4 + j], c[j]);
                }
                #pragma unroll
                for (int j = 0; j < 4; j++) {
                    float2 x = unpack2(c[j]);
                    float m = fmaxf(fmaxf(x.x, x.y), 0.0f);  // relu folded in
                    unsigned um = __reduce_max_sync(0xffffffffu, __float_as_uint(m));
                    if (lane == q * 4 + j) keep = max(keep, um);
                }
            }
        }
        // one RED per lane, 16 lanes in parallel
        if (lane < NH)
            atomicMax(&g_segmax[wseg * NH + lane], keep);
    } else {
        // rare: segment boundary inside this warp — per-point atomics
        int segs[4] = {bb.x, bb.y, bb.z, bb.w};
        #pragma unroll
        for (int p = 0; p < 2; p++) {
            unsigned long long a[NH];
            #pragma unroll
            for (int j = 0; j < NH; j++) a[j] = sB1[j];
            #pragma unroll
            for (int k = 0; k < 4; k++) {
                #pragma unroll
                for (int j = 0; j < NH; j++)
                    a[j] = fma2(fp[p][k], sW1[k * NH + j], a[j]);
            }
            #pragma unroll
            for (int j = 0; j < NH; j++) a[j] = relu2(a[j]);

            #pragma unroll
            for (int q = 0; q < 4; q++) {
                unsigned long long c[4];
                #pragma unroll
                for (int j = 0; j < 4; j++) c[j] = sB2[q * 4 + j];
                #pragma unroll
                for (int k = 0; k < NH; k++) {
                    #pragma unroll
                    for (int j = 0; j < 4; j++)
                        c[j] = fma2(a[k], sW2[k * NH + q * 4 + j], c[j]);
                }
                #pragma unroll
                for (int j = 0; j < 4; j++) {
                    float2 x = unpack2(c[j]);
                    atomicMax(&g_segmax[segs[2 * p + 0] * NH + q * 4 + j],
                              __float_as_uint(fmaxf(x.x, 0.0f)));
                    atomicMax(&g_segmax[segs[2 * p + 1] * NH + q * 4 + j],
                              __float_as_uint(fmaxf(x.y, 0.0f)));
                }
            }
        }
    }
}

__global__ void gate_kernel(const float* __restrict__ Wg,
                            const float* __restrict__ bg,
                            const float* __restrict__ gumbels)
{
    int b = threadIdx.x;
    if (b < NB) {
        float l0 = bg[0] + gumbels[2 * b + 0];
        float l1 = bg[1] + gumbels[2 * b + 1];
        #pragma unroll
        for (int k = 0; k < NH; k++) {
            float sf = __uint_as_float(g_segmax[b * NH + k]);
            l0 += sf * Wg[2 * k + 0];
            l1 += sf * Wg[2 * k + 1];
        }
        l0 *= (1.0f / TAU);
        l1 *= (1.0f / TAU);
        float m = fmaxf(l0, l1);
        float e0 = expf(l0 - m);
        float e1 = expf(l1 - m);
        g_gate[b] = e1 / (e0 + e1);
    }
}

__global__ __launch_bounds__(256) void scale_kernel(
    const float* __restrict__ refl, const int* __restrict__ batch,
    float* __restrict__ out, int n)
{
    __shared__ float sg[NB];
    if (threadIdx.x < NB) sg[threadIdx.x] = g_gate[threadIdx.x];
    __syncthreads();

    const int t = blockIdx.x * blockDim.x + threadIdx.x;
    const long base = 4L * t;
    if (base + 3 < (long)n) {
        float4 r = reinterpret_cast<const float4*>(refl)[t];
        int4 b = reinterpret_cast<const int4*>(batch)[t];
        float4 o;
        o.x = sg[b.x] * r.x;
        o.y = sg[b.y] * r.y;
        o.z = sg[b.z] * r.z;
        o.w = sg[b.w] * r.w;
        reinterpret_cast<float4*>(out)[t] = o;
    } else {
        for (long p = base; p < (long)n; ++p) out[p] = sg[batch[p]] * refl[p];
    }
}

extern "C" void kernel_launch(void* const* d_in, const int* in_sizes, int n_in,
                              void* d_out, int out_size)
{
    const float* pos     = (const float*)d_in[0];
    const float* refl    = (const float*)d_in[1];
    const int*   batch   = (const int*)d_in[2];
    const float* gumbels = (const float*)d_in[3];
    const float* W1      = (const float*)d_in[4];
    const float* b1      = (const float*)d_in[5];
    const float* W2      = (const float*)d_in[6];
    const float* b2      = (const float*)d_in[7];
    const float* Wg      = (const float*)d_in[8];
    const float* bg      = (const float*)d_in[9];
    float* out = (float*)d_out;

    const int n = in_sizes[1];  // N
    const int blocks = (n + 1023) / 1024;  // 256 threads x 4 points

    // mlp stays the 4th user launch so ncu (-s 5 -c 1) captures it
    init_kernel<<<1, NB * NH>>>();
    dummyA_kernel<<<1, 32>>>();
    dummyB_kernel<<<1, 32>>>();
    mlp_seg_kernel<<<blocks, 256>>>(pos, refl, batch, W1, b1, W2, b2, n);
    gate_kernel<<<1, NB>>>(Wg, bg, gumbels);
    scale_kernel<<<blocks, 256>>>(refl, batch, out, n);
}

// round 15
// speedup vs baseline: 9.4539x; 9.4539x over previous
#include <cuda_runtime.h>

#define NB 64
#define NH 16
#define TAU 1.0f

__device__ unsigned int g_segmax[NB * NH];  // float bits; all >= 0 (post-ReLU)
__device__ float g_gate[NB];

// ---------- packed f32x2 helpers ----------
__device__ __forceinline__ unsigned long long pack2(float lo, float hi) {
    unsigned long long r;
    asm("mov.b64 %0, {%1, %2};" : "=l"(r) : "f"(lo), "f"(hi));
    return r;
}
__device__ __forceinline__ float2 unpack2(unsigned long long p) {
    float2 f;
    asm("mov.b64 {%0, %1}, %2;" : "=f"(f.x), "=f"(f.y) : "l"(p));
    return f;
}
__device__ __forceinline__ unsigned long long fma2(unsigned long long a,
                                                   unsigned long long b,
                                                   unsigned long long c) {
    unsigned long long d;
    asm("fma.rn.f32x2 %0, %1, %2, %3;" : "=l"(d) : "l"(a), "l"(b), "l"(c));
    return d;
}
__device__ __forceinline__ unsigned long long relu2(unsigned long long p) {
    float2 f = unpack2(p);
    return pack2(fmaxf(f.x, 0.0f), fmaxf(f.y, 0.0f));
}
__device__ __forceinline__ float lo2(unsigned long long p) { return unpack2(p).x; }

// ---------- kernels ----------
__global__ void init_kernel() {
    int i = threadIdx.x;
    if (i < NB * NH) g_segmax[i] = 0u;
}

__global__ void dummyA_kernel() {}
__global__ void dummyB_kernel() {}

// Persistent blocks: weights loaded once per block, grid-stride over 1024-pt tiles.
// Body is the proven R8 kernel (128 regs, no spill).
__global__ __launch_bounds__(256, 2) void mlp_seg_kernel(
    const float* __restrict__ pos, const float* __restrict__ refl,
    const int* __restrict__ batch,
    const float* __restrict__ W1, const float* __restrict__ b1,
    const float* __restrict__ W2, const float* __restrict__ b2,
    int n, int ntiles)
{
    // weights pre-duplicated into b64 pairs so one LDS.64 feeds both packed halves
    __shared__ unsigned long long sW1[4 * NH];
    __shared__ unsigned long long sB1[NH];
    __shared__ unsigned long long sW2[NH * NH];
    __shared__ unsigned long long sB2[NH];

    for (int i = threadIdx.x; i < 4 * NH + NH + NH * NH + NH; i += blockDim.x) {
        float w;
        if (i < 64)       { w = W1[i];       sW1[i]       = pack2(w, w); }
        else if (i < 80)  { w = b1[i - 64];  sB1[i - 64]  = pack2(w, w); }
        else if (i < 336) { w = W2[i - 80];  sW2[i - 80]  = pack2(w, w); }
        else              { w = b2[i - 336]; sB2[i - 336] = pack2(w, w); }
    }
    __syncthreads();

    const int lane = threadIdx.x & 31;

    for (int tile = blockIdx.x; tile < ntiles; tile += gridDim.x) {
        const int t = tile * 256 + threadIdx.x;
        const long base = 4L * t;
        const bool full4 = (base + 3 < (long)n);

        if (!full4) {
            // tail: fully scalar (usually never taken: N % 4 == 0)
            for (long p = base; p < (long)n; ++p) {
                float f[4] = {pos[3 * p + 0], pos[3 * p + 1], pos[3 * p + 2], refl[p]};
                float h1[NH];
                #pragma unroll
                for (int j = 0; j < NH; j++) {
                    float s = lo2(sB1[j]);
                    #pragma unroll
                    for (int k = 0; k < 4; k++) s += f[k] * lo2(sW1[k * NH + j]);
                    h1[j] = fmaxf(s, 0.0f);
                }
                int sgi = batch[p];
                #pragma unroll
                for (int j = 0; j < NH; j++) {
                    float s = lo2(sB2[j]);
                    #pragma unroll
                    for (int k = 0; k < NH; k++) s += h1[k] * lo2(sW2[k * NH + j]);
                    s = fmaxf(s, 0.0f);
                    atomicMax(&g_segmax[sgi * NH + j], __float_as_uint(s));
                }
            }
            continue;
        }

        const float4* pos4 = reinterpret_cast<const float4*>(pos);
        float4 v0 = pos4[3 * t + 0];
        float4 v1 = pos4[3 * t + 1];
        float4 v2 = pos4[3 * t + 2];
        float4 r  = reinterpret_cast<const float4*>(refl)[t];
        int4  bb  = reinterpret_cast<const int4*>(batch)[t];

        // warp-uniform segment check (batch sorted: bb.x == bb.w => all 4 equal)
        const int  wseg = __shfl_sync(0xffffffffu, bb.x, 0);
        const bool wuni = __all_sync(0xffffffffu, (bb.x == bb.w) && (bb.x == wseg));

        // features packed across point pairs: pair0=(p0,p1), pair1=(p2,p3)
        unsigned long long f0[4], f1[4];
        f0[0] = pack2(v0.x, v0.w); f0[1] = pack2(v0.y, v1.x);
        f0[2] = pack2(v0.z, v1.y); f0[3] = pack2(r.x,  r.y);
        f1[0] = pack2(v1.z, v2.y); f1[1] = pack2(v1.w, v2.z);
        f1[2] = pack2(v2.x, v2.w); f1[3] = pack2(r.z,  r.w);

        // layer 1: [4] -> [16], both pairs
        unsigned long long a0[NH], a1[NH];
        #pragma unroll
        for (int j = 0; j < NH; j++) { a0[j] = sB1[j]; a1[j] = sB1[j]; }
        #pragma unroll
        for (int k = 0; k < 4; k++) {
            #pragma unroll
            for (int j = 0; j < NH; j++) {
                unsigned long long w = sW1[k * NH + j];
                a0[j] = fma2(f0[k], w, a0[j]);
                a1[j] = fma2(f1[k], w, a1[j]);
            }
        }
        #pragma unroll
        for (int j = 0; j < NH; j++) { a0[j] = relu2(a0[j]); a1[j] = relu2(a1[j]); }

        // layer 2 in j-quarters to bound live registers
        if (wuni) {
            unsigned keep = 0u;  // lane j (<16) holds warp-max of feature j
            #pragma unroll
            for (int q = 0; q < 4; q++) {
                unsigned long long c0[4], c1[4];
                #pragma unroll
                for (int j = 0; j < 4; j++) { c0[j] = sB2[q * 4 + j]; c1[j] = c0[j]; }
                #pragma unroll
                for (int k = 0; k < NH; k++) {
                    #pragma unroll
                    for (int j = 0; j < 4; j++) {
                        unsigned long long w = sW2[k * NH + q * 4 + j];
                        c0[j] = fma2(a0[k], w, c0[j]);
                        c1[j] = fma2(a1[k], w, c1[j]);
                    }
                }
                #pragma unroll
                for (int j = 0; j < 4; j++) {
                    float2 x = unpack2(c0[j]);
                    float2 y = unpack2(c1[j]);
                    float m = fmaxf(fmaxf(fmaxf(x.x, x.y), fmaxf(y.x, y.y)), 0.0f);
                    unsigned um = __reduce_max_sync(0xffffffffu, __float_as_uint(m));
                    if (lane == q * 4 + j) keep = um;
                }
            }
            // one RED per lane, 16 lanes in parallel
            if (lane < NH)
                atomicMax(&g_segmax[wseg * NH + lane], keep);
        } else {
            // rare: segment boundary inside this warp — per-point atomics
            int segs[4] = {bb.x, bb.y, bb.z, bb.w};
            #pragma unroll
            for (int q = 0; q < 4; q++) {
                unsigned long long c0[4], c1[4];
                #pragma unroll
                for (int j = 0; j < 4; j++) { c0[j] = sB2[q * 4 + j]; c1[j] = c0[j]; }
                #pragma unroll
                for (int k = 0; k < NH; k++) {
                    #pragma unroll
                    for (int j = 0; j < 4; j++) {
                        unsigned long long w = sW2[k * NH + q * 4 + j];
                        c0[j] = fma2(a0[k], w, c0[j]);
                        c1[j] = fma2(a1[k], w, c1[j]);
                    }
                }
                #pragma unroll
                for (int j = 0; j < 4; j++) {
                    float2 x = unpack2(c0[j]);
                    float2 y = unpack2(c1[j]);
                    float v[4] = {fmaxf(x.x, 0.0f), fmaxf(x.y, 0.0f),
                                  fmaxf(y.x, 0.0f), fmaxf(y.y, 0.0f)};
                    #pragma unroll
                    for (int p = 0; p < 4; p++)
                        atomicMax(&g_segmax[segs[p] * NH + q * 4 + j],
                                  __float_as_uint(v[p]));
                }
            }
        }
    }
}

__global__ void gate_kernel(const float* __restrict__ Wg,
                            const float* __restrict__ bg,
                            const float* __restrict__ gumbels)
{
    int b = threadIdx.x;
    if (b < NB) {
        float l0 = bg[0] + gumbels[2 * b + 0];
        float l1 = bg[1] + gumbels[2 * b + 1];
        #pragma unroll
        for (int k = 0; k < NH; k++) {
            float sf = __uint_as_float(g_segmax[b * NH + k]);
            l0 += sf * Wg[2 * k + 0];
            l1 += sf * Wg[2 * k + 1];
        }
        l0 *= (1.0f / TAU);
        l1 *= (1.0f / TAU);
        float m = fmaxf(l0, l1);
        float e0 = expf(l0 - m);
        float e1 = expf(l1 - m);
        g_gate[b] = e1 / (e0 + e1);
    }
}

__global__ __launch_bounds__(256) void scale_kernel(
    const float* __restrict__ refl, const int* __restrict__ batch,
    float* __restrict__ out, int n)
{
    __shared__ float sg[NB];
    if (threadIdx.x < NB) sg[threadIdx.x] = g_gate[threadIdx.x];
    __syncthreads();

    const int t = blockIdx.x * blockDim.x + threadIdx.x;
    const long base = 4L * t;
    if (base + 3 < (long)n) {
        float4 r = reinterpret_cast<const float4*>(refl)[t];
        int4 b = reinterpret_cast<const int4*>(batch)[t];
        float4 o;
        o.x = sg[b.x] * r.x;
        o.y = sg[b.y] * r.y;
        o.z = sg[b.z] * r.z;
        o.w = sg[b.w] * r.w;
        reinterpret_cast<float4*>(out)[t] = o;
    } else {
        for (long p = base; p < (long)n; ++p) out[p] = sg[batch[p]] * refl[p];
    }
}

extern "C" void kernel_launch(void* const* d_in, const int* in_sizes, int n_in,
                              void* d_out, int out_size)
{
    const float* pos     = (const float*)d_in[0];
    const float* refl    = (const float*)d_in[1];
    const int*   batch   = (const int*)d_in[2];
    const float* gumbels = (const float*)d_in[3];
    const float* W1      = (const float*)d_in[4];
    const float* b1      = (const float*)d_in[5];
    const float* W2      = (const float*)d_in[6];
    const float* b2      = (const float*)d_in[7];
    const float* Wg      = (const float*)d_in[8];
    const float* bg      = (const float*)d_in[9];
    float* out = (float*)d_out;

    const int n = in_sizes[1];  // N
    const int ntiles = (n + 1023) / 1024;       // 1024 points per tile
    const int persist = 296;                    // 148 SMs x 2 resident blocks
    const int mlp_blocks = ntiles < persist ? ntiles : persist;
    const int scale_blocks = ntiles;

    // mlp stays the 4th user launch so ncu (-s 5 -c 1) captures it
    init_kernel<<<1, NB * NH>>>();
    dummyA_kernel<<<1, 32>>>();
    dummyB_kernel<<<1, 32>>>();
    mlp_seg_kernel<<<mlp_blocks, 256>>>(pos, refl, batch, W1, b1, W2, b2, n, ntiles);
    gate_kernel<<<1, NB>>>(Wg, bg, gumbels);
    scale_kernel<<<scale_blocks, 256>>>(refl, batch, out, n);
}